// round 1
// baseline (speedup 1.0000x reference)
#include <cuda_runtime.h>

// Shapes (fixed by the problem)
#define BB 4
#define CC 256
#define TT 2048
#define HH 8
#define DD 32
#define M3 768   // 3*C

// Scratch (device globals; no allocation in kernel_launch)
__device__ float g_norm[BB * CC * TT];   // 8.4 MB
__device__ float g_qkv [BB * M3 * TT];   // 25.2 MB
__device__ float g_att [BB * CC * TT];   // 8.4 MB

// ---------------------------------------------------------------------------
// Kernel 1: GroupNorm. One block per (b, g). 32 groups x 8 channels x 2048.
// ---------------------------------------------------------------------------
__global__ void gn_kernel(const float* __restrict__ x,
                          const float* __restrict__ w,
                          const float* __restrict__ bias) {
    int bg = blockIdx.x;
    int bb = bg >> 5, g = bg & 31;
    const float4* xp = (const float4*)(x + ((size_t)bb * CC + g * 8) * TT);
    int tid = threadIdx.x;

    float s = 0.f, s2 = 0.f;
    for (int i = tid; i < 4096; i += 256) {   // 16384 floats = 4096 float4
        float4 v = xp[i];
        s  += v.x + v.y + v.z + v.w;
        s2 += v.x * v.x + v.y * v.y + v.z * v.z + v.w * v.w;
    }
    __shared__ float rs[256], rs2[256];
    rs[tid] = s; rs2[tid] = s2;
    __syncthreads();
    for (int off = 128; off > 0; off >>= 1) {
        if (tid < off) { rs[tid] += rs[tid + off]; rs2[tid] += rs2[tid + off]; }
        __syncthreads();
    }
    float mu   = rs[0] * (1.f / 16384.f);
    float var  = rs2[0] * (1.f / 16384.f) - mu * mu;
    float rstd = rsqrtf(var + 1e-5f);

    float4* op = (float4*)(g_norm + ((size_t)bb * CC + g * 8) * TT);
    for (int i = tid; i < 4096; i += 256) {
        int c = g * 8 + (i >> 9);            // 512 float4 per channel row
        float wc = w[c] * rstd;
        float bc = bias[c] - mu * wc;
        float4 v = xp[i];
        float4 o;
        o.x = v.x * wc + bc;
        o.y = v.y * wc + bc;
        o.z = v.z * wc + bc;
        o.w = v.w * wc + bc;
        op[i] = o;
    }
}

// ---------------------------------------------------------------------------
// Kernel 2: QKV projection GEMM. qkv[b,o,t] = sum_c qkv_w[o,c] * norm[b,c,t]
// Tile 64x64, K-step 16, 256 threads, 4x4 per thread.
// ---------------------------------------------------------------------------
__global__ void qkv_gemm_kernel(const float* __restrict__ A /* [768,256] */) {
    int batch = blockIdx.z;
    const float* Bm = g_norm + (size_t)batch * CC * TT;
    float*       Cm = g_qkv  + (size_t)batch * M3 * TT;
    int n0 = blockIdx.x * 64, m0 = blockIdx.y * 64;

    __shared__ __align__(16) float As[16][68];
    __shared__ __align__(16) float Bs[16][68];

    int tid = threadIdx.x;
    int ty = tid >> 4, tx = tid & 15;
    float acc[4][4] = {};

    for (int k0 = 0; k0 < CC; k0 += 16) {
        {   // A tile: 64(m) x 16(k), transposed into As[k][m]
            int row = tid >> 2, cg = tid & 3;
            float4 a = *(const float4*)(A + (size_t)(m0 + row) * CC + k0 + cg * 4);
            As[cg * 4 + 0][row] = a.x;
            As[cg * 4 + 1][row] = a.y;
            As[cg * 4 + 2][row] = a.z;
            As[cg * 4 + 3][row] = a.w;
        }
        {   // B tile: 16(k) x 64(n)
            int row = tid >> 4, cg = tid & 15;
            *(float4*)&Bs[row][cg * 4] =
                *(const float4*)(Bm + (size_t)(k0 + row) * TT + n0 + cg * 4);
        }
        __syncthreads();
        #pragma unroll
        for (int kk = 0; kk < 16; kk++) {
            float4 a  = *(const float4*)&As[kk][ty * 4];
            float4 bv = *(const float4*)&Bs[kk][tx * 4];
            acc[0][0] += a.x * bv.x; acc[0][1] += a.x * bv.y; acc[0][2] += a.x * bv.z; acc[0][3] += a.x * bv.w;
            acc[1][0] += a.y * bv.x; acc[1][1] += a.y * bv.y; acc[1][2] += a.y * bv.z; acc[1][3] += a.y * bv.w;
            acc[2][0] += a.z * bv.x; acc[2][1] += a.z * bv.y; acc[2][2] += a.z * bv.z; acc[2][3] += a.z * bv.w;
            acc[3][0] += a.w * bv.x; acc[3][1] += a.w * bv.y; acc[3][2] += a.w * bv.z; acc[3][3] += a.w * bv.w;
        }
        __syncthreads();
    }
    #pragma unroll
    for (int i = 0; i < 4; i++) {
        float4 o = make_float4(acc[i][0], acc[i][1], acc[i][2], acc[i][3]);
        *(float4*)(Cm + (size_t)(m0 + ty * 4 + i) * TT + n0 + tx * 4) = o;
    }
}

// ---------------------------------------------------------------------------
// Kernel 3: flash attention per (b, h, l-tile of 64). Online softmax.
// qkv layout per head: rows [h*96 .. h*96+31]=Q, [+32..63]=K, [+64..95]=V.
// scale = 1/sqrt(C) = 1/16.
// ---------------------------------------------------------------------------
__global__ void attn_kernel() {
    int lt = blockIdx.x, h = blockIdx.y, batch = blockIdx.z;
    int l0 = lt * 64;
    const float* qp = g_qkv + ((size_t)batch * M3 + h * 96) * TT;
    const float* kp = qp + 32 * (size_t)TT;
    const float* vp = qp + 64 * (size_t)TT;

    __shared__ __align__(16) float Qs[32][68];
    __shared__ __align__(16) float Ks[32][68];
    __shared__ __align__(16) float Vs[32][68];
    __shared__ __align__(16) float Ps[64][68];
    __shared__ float m_s[64], l_s[64], alpha_s[64], red[64][4];

    int tid = threadIdx.x;
    int ty = tid >> 4, tx = tid & 15;

    // Load Q tile [32 d][64 l]
    #pragma unroll
    for (int t = 0; t < 2; t++) {
        int f = tid + t * 256;
        int row = f >> 4, cg = f & 15;
        *(float4*)&Qs[row][cg * 4] = *(const float4*)(qp + (size_t)row * TT + l0 + cg * 4);
    }
    if (tid < 64) { m_s[tid] = -1e30f; l_s[tid] = 0.f; }

    float O[4][2] = {};   // 4 l-rows (ty*4+i) x 2 d-cols (tx*2+j)

    for (int xt = 0; xt < 32; xt++) {
        __syncthreads();   // protect Ks/Vs/Ps from previous iteration's readers
        int x0 = xt * 64;
        #pragma unroll
        for (int t = 0; t < 2; t++) {
            int f = tid + t * 256;
            int row = f >> 4, cg = f & 15;
            *(float4*)&Ks[row][cg * 4] = *(const float4*)(kp + (size_t)row * TT + x0 + cg * 4);
            *(float4*)&Vs[row][cg * 4] = *(const float4*)(vp + (size_t)row * TT + x0 + cg * 4);
        }
        __syncthreads();

        // S = Q^T K * (1/16) -> Ps[l][x]
        float acc[4][4] = {};
        #pragma unroll
        for (int d = 0; d < 32; d++) {
            float4 a  = *(const float4*)&Qs[d][ty * 4];
            float4 bv = *(const float4*)&Ks[d][tx * 4];
            acc[0][0] += a.x * bv.x; acc[0][1] += a.x * bv.y; acc[0][2] += a.x * bv.z; acc[0][3] += a.x * bv.w;
            acc[1][0] += a.y * bv.x; acc[1][1] += a.y * bv.y; acc[1][2] += a.y * bv.z; acc[1][3] += a.y * bv.w;
            acc[2][0] += a.z * bv.x; acc[2][1] += a.z * bv.y; acc[2][2] += a.z * bv.z; acc[2][3] += a.z * bv.w;
            acc[3][0] += a.w * bv.x; acc[3][1] += a.w * bv.y; acc[3][2] += a.w * bv.z; acc[3][3] += a.w * bv.w;
        }
        #pragma unroll
        for (int i = 0; i < 4; i++) {
            float4 o = make_float4(acc[i][0] * 0.0625f, acc[i][1] * 0.0625f,
                                   acc[i][2] * 0.0625f, acc[i][3] * 0.0625f);
            *(float4*)&Ps[ty * 4 + i][tx * 4] = o;
        }
        __syncthreads();

        // Row max (4 partials per row)
        {
            int row = tid >> 2, seg = tid & 3;
            float mx = -1e30f;
            #pragma unroll
            for (int c = 0; c < 16; c++) mx = fmaxf(mx, Ps[row][seg * 16 + c]);
            red[row][seg] = mx;
        }
        __syncthreads();
        if (tid < 64) {
            float tm = fmaxf(fmaxf(red[tid][0], red[tid][1]), fmaxf(red[tid][2], red[tid][3]));
            float mo = m_s[tid];
            float mn = fmaxf(mo, tm);
            alpha_s[tid] = __expf(mo - mn);
            m_s[tid] = mn;
        }
        __syncthreads();

        // exp + row sum partials
        {
            int row = tid >> 2, seg = tid & 3;
            float mn = m_s[row];
            float sm = 0.f;
            #pragma unroll
            for (int c = 0; c < 16; c++) {
                float e = __expf(Ps[row][seg * 16 + c] - mn);
                Ps[row][seg * 16 + c] = e;
                sm += e;
            }
            red[row][seg] = sm;
        }
        __syncthreads();
        if (tid < 64)
            l_s[tid] = l_s[tid] * alpha_s[tid] + red[tid][0] + red[tid][1] + red[tid][2] + red[tid][3];

        // O = alpha*O + P @ V^T
        #pragma unroll
        for (int i = 0; i < 4; i++) {
            float al = alpha_s[ty * 4 + i];
            O[i][0] *= al; O[i][1] *= al;
        }
        #pragma unroll
        for (int x = 0; x < 64; x += 4) {
            float4 v0 = *(const float4*)&Vs[tx * 2 + 0][x];
            float4 v1 = *(const float4*)&Vs[tx * 2 + 1][x];
            #pragma unroll
            for (int i = 0; i < 4; i++) {
                float4 p = *(const float4*)&Ps[ty * 4 + i][x];
                O[i][0] += p.x * v0.x + p.y * v0.y + p.z * v0.z + p.w * v0.w;
                O[i][1] += p.x * v1.x + p.y * v1.y + p.z * v1.z + p.w * v1.w;
            }
        }
    }
    __syncthreads();   // l_s final, and done reading Ks

    // Normalize and stage transposed into Ks[d][l] for coalesced stores
    #pragma unroll
    for (int i = 0; i < 4; i++) {
        int l = ty * 4 + i;
        float inv = 1.f / l_s[l];
        Ks[tx * 2 + 0][l] = O[i][0] * inv;
        Ks[tx * 2 + 1][l] = O[i][1] * inv;
    }
    __syncthreads();
    float* op = g_att + ((size_t)batch * CC + h * 32) * TT;
    #pragma unroll
    for (int t = 0; t < 2; t++) {
        int f = tid + t * 256;
        int row = f >> 4, cg = f & 15;
        *(float4*)(op + (size_t)row * TT + l0 + cg * 4) = *(const float4*)&Ks[row][cg * 4];
    }
}

// ---------------------------------------------------------------------------
// Kernel 4: out projection + bias + residual.
// y[b,o,t] = sum_c out_w[o,c]*att[b,c,t] + out_b[o] + x[b,o,t]
// ---------------------------------------------------------------------------
__global__ void out_gemm_kernel(const float* __restrict__ A /* [256,256] */,
                                const float* __restrict__ ob,
                                const float* __restrict__ xres,
                                float* __restrict__ out) {
    int batch = blockIdx.z;
    const float* Bm = g_att + (size_t)batch * CC * TT;
    const float* Xm = xres  + (size_t)batch * CC * TT;
    float*       Cm = out   + (size_t)batch * CC * TT;
    int n0 = blockIdx.x * 64, m0 = blockIdx.y * 64;

    __shared__ __align__(16) float As[16][68];
    __shared__ __align__(16) float Bs[16][68];

    int tid = threadIdx.x;
    int ty = tid >> 4, tx = tid & 15;
    float acc[4][4] = {};

    for (int k0 = 0; k0 < CC; k0 += 16) {
        {
            int row = tid >> 2, cg = tid & 3;
            float4 a = *(const float4*)(A + (size_t)(m0 + row) * CC + k0 + cg * 4);
            As[cg * 4 + 0][row] = a.x;
            As[cg * 4 + 1][row] = a.y;
            As[cg * 4 + 2][row] = a.z;
            As[cg * 4 + 3][row] = a.w;
        }
        {
            int row = tid >> 4, cg = tid & 15;
            *(float4*)&Bs[row][cg * 4] =
                *(const float4*)(Bm + (size_t)(k0 + row) * TT + n0 + cg * 4);
        }
        __syncthreads();
        #pragma unroll
        for (int kk = 0; kk < 16; kk++) {
            float4 a  = *(const float4*)&As[kk][ty * 4];
            float4 bv = *(const float4*)&Bs[kk][tx * 4];
            acc[0][0] += a.x * bv.x; acc[0][1] += a.x * bv.y; acc[0][2] += a.x * bv.z; acc[0][3] += a.x * bv.w;
            acc[1][0] += a.y * bv.x; acc[1][1] += a.y * bv.y; acc[1][2] += a.y * bv.z; acc[1][3] += a.y * bv.w;
            acc[2][0] += a.z * bv.x; acc[2][1] += a.z * bv.y; acc[2][2] += a.z * bv.z; acc[2][3] += a.z * bv.w;
            acc[3][0] += a.w * bv.x; acc[3][1] += a.w * bv.y; acc[3][2] += a.w * bv.z; acc[3][3] += a.w * bv.w;
        }
        __syncthreads();
    }
    #pragma unroll
    for (int i = 0; i < 4; i++) {
        int m = m0 + ty * 4 + i;
        float bsv = ob[m];
        size_t off = (size_t)m * TT + n0 + tx * 4;
        float4 r = *(const float4*)(Xm + off);
        float4 o = make_float4(acc[i][0] + bsv + r.x, acc[i][1] + bsv + r.y,
                               acc[i][2] + bsv + r.z, acc[i][3] + bsv + r.w);
        *(float4*)(Cm + off) = o;
    }
}

// ---------------------------------------------------------------------------
extern "C" void kernel_launch(void* const* d_in, const int* in_sizes, int n_in,
                              void* d_out, int out_size) {
    const float* x     = (const float*)d_in[0];
    const float* gn_w  = (const float*)d_in[1];
    const float* gn_b  = (const float*)d_in[2];
    const float* qkv_w = (const float*)d_in[3];
    const float* out_w = (const float*)d_in[4];
    const float* out_b = (const float*)d_in[5];
    float* out = (float*)d_out;

    gn_kernel<<<BB * 32, 256>>>(x, gn_w, gn_b);
    qkv_gemm_kernel<<<dim3(TT / 64, M3 / 64, BB), 256>>>(qkv_w);
    attn_kernel<<<dim3(TT / 64, HH, BB), 256>>>();
    out_gemm_kernel<<<dim3(TT / 64, CC / 64, BB), 256>>>(out_w, out_b, x, out);
}

// round 2
// speedup vs baseline: 1.5691x; 1.5691x over previous
#include <cuda_runtime.h>
#include <cuda_bf16.h>
#include <cstdint>

// Shapes (fixed by the problem)
#define BB 4
#define CC 256
#define TT 2048
#define HH 8
#define DD 32
#define M3 768   // 3*C

// Scratch (device globals; no allocation in kernel_launch)
__device__ float g_norm[BB * CC * TT];   // 8.4 MB
__device__ float g_qkv [BB * M3 * TT];   // 25.2 MB
__device__ float g_att [BB * CC * TT];   // 8.4 MB

// ---------------------------------------------------------------------------
// Helpers: ldmatrix / mma / bf16 split packing
// ---------------------------------------------------------------------------
__device__ __forceinline__ uint32_t su(const void* p) {
    uint32_t a;
    asm("{ .reg .u64 t; cvta.to.shared.u64 t, %1; cvt.u32.u64 %0, t; }"
        : "=r"(a) : "l"(p));
    return a;
}

__device__ __forceinline__ void ldsm4(uint32_t& d0, uint32_t& d1,
                                      uint32_t& d2, uint32_t& d3, uint32_t addr) {
    asm volatile("ldmatrix.sync.aligned.m8n8.x4.shared.b16 {%0,%1,%2,%3}, [%4];"
                 : "=r"(d0), "=r"(d1), "=r"(d2), "=r"(d3) : "r"(addr));
}

__device__ __forceinline__ void mma16816(float* c,
                                         uint32_t a0, uint32_t a1, uint32_t a2, uint32_t a3,
                                         uint32_t b0, uint32_t b1) {
    asm volatile("mma.sync.aligned.m16n8k16.row.col.f32.bf16.bf16.f32 "
                 "{%0,%1,%2,%3}, {%4,%5,%6,%7}, {%8,%9}, {%0,%1,%2,%3};"
                 : "+f"(c[0]), "+f"(c[1]), "+f"(c[2]), "+f"(c[3])
                 : "r"(a0), "r"(a1), "r"(a2), "r"(a3), "r"(b0), "r"(b1));
}

__device__ __forceinline__ void split2(float x, float y, uint32_t& hi, uint32_t& lo) {
    __nv_bfloat16 hx = __float2bfloat16(x);
    __nv_bfloat16 hy = __float2bfloat16(y);
    float rx = x - __bfloat162float(hx);
    float ry = y - __bfloat162float(hy);
    __nv_bfloat162 H; H.x = hx; H.y = hy;
    __nv_bfloat162 L; L.x = __float2bfloat16(rx); L.y = __float2bfloat16(ry);
    hi = *(uint32_t*)&H;
    lo = *(uint32_t*)&L;
}

// ---------------------------------------------------------------------------
// Kernel 1: GroupNorm. One block per (b, g). 32 groups x 8 channels x 2048.
// ---------------------------------------------------------------------------
__global__ void gn_kernel(const float* __restrict__ x,
                          const float* __restrict__ w,
                          const float* __restrict__ bias) {
    int bg = blockIdx.x;
    int bb = bg >> 5, g = bg & 31;
    const float4* xp = (const float4*)(x + ((size_t)bb * CC + g * 8) * TT);
    int tid = threadIdx.x;

    float s = 0.f, s2 = 0.f;
    for (int i = tid; i < 4096; i += 256) {
        float4 v = xp[i];
        s  += v.x + v.y + v.z + v.w;
        s2 += v.x * v.x + v.y * v.y + v.z * v.z + v.w * v.w;
    }
    __shared__ float rs[256], rs2[256];
    rs[tid] = s; rs2[tid] = s2;
    __syncthreads();
    for (int off = 128; off > 0; off >>= 1) {
        if (tid < off) { rs[tid] += rs[tid + off]; rs2[tid] += rs2[tid + off]; }
        __syncthreads();
    }
    float mu   = rs[0] * (1.f / 16384.f);
    float var  = rs2[0] * (1.f / 16384.f) - mu * mu;
    float rstd = rsqrtf(var + 1e-5f);

    float4* op = (float4*)(g_norm + ((size_t)bb * CC + g * 8) * TT);
    for (int i = tid; i < 4096; i += 256) {
        int c = g * 8 + (i >> 9);
        float wc = w[c] * rstd;
        float bc = bias[c] - mu * wc;
        float4 v = xp[i];
        float4 o;
        o.x = v.x * wc + bc;
        o.y = v.y * wc + bc;
        o.z = v.z * wc + bc;
        o.w = v.w * wc + bc;
        op[i] = o;
    }
}

// ---------------------------------------------------------------------------
// Kernel 2: QKV projection GEMM (SIMT fp32 64x64 tile).
// ---------------------------------------------------------------------------
__global__ void qkv_gemm_kernel(const float* __restrict__ A /* [768,256] */) {
    int batch = blockIdx.z;
    const float* Bm = g_norm + (size_t)batch * CC * TT;
    float*       Cm = g_qkv  + (size_t)batch * M3 * TT;
    int n0 = blockIdx.x * 64, m0 = blockIdx.y * 64;

    __shared__ __align__(16) float As[16][68];
    __shared__ __align__(16) float Bs[16][68];

    int tid = threadIdx.x;
    int ty = tid >> 4, tx = tid & 15;
    float acc[4][4] = {};

    for (int k0 = 0; k0 < CC; k0 += 16) {
        {
            int row = tid >> 2, cg = tid & 3;
            float4 a = *(const float4*)(A + (size_t)(m0 + row) * CC + k0 + cg * 4);
            As[cg * 4 + 0][row] = a.x;
            As[cg * 4 + 1][row] = a.y;
            As[cg * 4 + 2][row] = a.z;
            As[cg * 4 + 3][row] = a.w;
        }
        {
            int row = tid >> 4, cg = tid & 15;
            *(float4*)&Bs[row][cg * 4] =
                *(const float4*)(Bm + (size_t)(k0 + row) * TT + n0 + cg * 4);
        }
        __syncthreads();
        #pragma unroll
        for (int kk = 0; kk < 16; kk++) {
            float4 a  = *(const float4*)&As[kk][ty * 4];
            float4 bv = *(const float4*)&Bs[kk][tx * 4];
            acc[0][0] += a.x * bv.x; acc[0][1] += a.x * bv.y; acc[0][2] += a.x * bv.z; acc[0][3] += a.x * bv.w;
            acc[1][0] += a.y * bv.x; acc[1][1] += a.y * bv.y; acc[1][2] += a.y * bv.z; acc[1][3] += a.y * bv.w;
            acc[2][0] += a.z * bv.x; acc[2][1] += a.z * bv.y; acc[2][2] += a.z * bv.z; acc[2][3] += a.z * bv.w;
            acc[3][0] += a.w * bv.x; acc[3][1] += a.w * bv.y; acc[3][2] += a.w * bv.z; acc[3][3] += a.w * bv.w;
        }
        __syncthreads();
    }
    #pragma unroll
    for (int i = 0; i < 4; i++) {
        float4 o = make_float4(acc[i][0], acc[i][1], acc[i][2], acc[i][3]);
        *(float4*)(Cm + (size_t)(m0 + ty * 4 + i) * TT + n0 + tx * 4) = o;
    }
}

// ---------------------------------------------------------------------------
// Kernel 3: flash attention, bf16 split-precision tensor-core version.
// Block = 128 threads (4 warps), L-tile 64 (warp w owns rows w*16..w*16+15),
// X-tile 64, 32 x-iterations.
//
// Per-head layout in g_qkv: rows [h*96..+31]=Q, [+32..63]=K, [+64..95]=V,
// each [32 d][2048 t].  scale 1/16 folded into Q conversion.
//
// QK^T with split: K-dim concatenated to 96:
//   Qs chunks [hi, lo, hi] x Ks chunks [hi, hi, lo]
//   -> sum = Qhi*Khi + Qlo*Khi + Qhi*Klo  (lo*lo term ~2^-32, dropped)
// PV with split: 3 mmas (Phi*Vhi + Plo*Vhi + Phi*Vlo), P packed from the
// S accumulator fragments in registers (C-frag layout == A-frag layout).
// ---------------------------------------------------------------------------
__global__ void __launch_bounds__(128) attn_kernel() {
    int l0 = blockIdx.x * 64, h = blockIdx.y, batch = blockIdx.z;
    const float* qp = g_qkv + ((size_t)batch * M3 + h * 96) * TT;
    const float* kp = qp + 32 * (size_t)TT;
    const float* vp = qp + 64 * (size_t)TT;

    __shared__ __align__(16) __nv_bfloat16 Qs[64][104];  // 96 cols used
    __shared__ __align__(16) __nv_bfloat16 Ks[64][104];
    __shared__ __align__(16) __nv_bfloat16 Vh[32][72];   // 64 cols used
    __shared__ __align__(16) __nv_bfloat16 Vl[32][72];
    __shared__ __align__(16) float Os[64][33];

    int tid  = threadIdx.x;
    int lane = tid & 31;
    int warp = tid >> 5;
    int m0   = warp * 16;

    // Q tile: [d][l] -> transposed split into Qs[l][{hi,lo,hi}] with 1/16 scale
    for (int f = tid; f < 2048; f += 128) {
        int d = f >> 6, l = f & 63;
        float v = qp[(size_t)d * TT + l0 + l] * 0.0625f;
        __nv_bfloat16 hi = __float2bfloat16(v);
        __nv_bfloat16 lo = __float2bfloat16(v - __bfloat162float(hi));
        Qs[l][d] = hi; Qs[l][32 + d] = lo; Qs[l][64 + d] = hi;
    }

    float mrow[2] = { -1e30f, -1e30f };
    float lrow[2] = { 0.f, 0.f };
    float Of[4][4] = {};    // 4 n-tiles of d (8 each) x m16n8 C-frag

    int al = lane & 15;          // ldmatrix A row select
    int ah = (lane >> 4) * 8;    // ldmatrix A col half
    int b4 = lane & 7;           // ldmatrix B x4 row-within-tile
    int bg = lane >> 3;          // 0..3 address group

    for (int xt = 0; xt < 32; xt++) {
        __syncthreads();   // previous iteration's readers done with Ks/Vh/Vl
        int x0 = xt * 64;
        for (int f = tid; f < 2048; f += 128) {
            int d = f >> 6, x = f & 63;
            float kv = kp[(size_t)d * TT + x0 + x];
            __nv_bfloat16 khi = __float2bfloat16(kv);
            __nv_bfloat16 klo = __float2bfloat16(kv - __bfloat162float(khi));
            Ks[x][d] = khi; Ks[x][32 + d] = khi; Ks[x][64 + d] = klo;
            float vv = vp[(size_t)d * TT + x0 + x];
            __nv_bfloat16 vhi = __float2bfloat16(vv);
            Vh[d][x] = vhi;
            Vl[d][x] = __float2bfloat16(vv - __bfloat162float(vhi));
        }
        __syncthreads();

        // ---- S = Q^T K (scaled), K-dim 96 ----
        float Sf[8][4] = {};
        #pragma unroll
        for (int kc = 0; kc < 6; kc++) {
            int kb = kc * 16;
            uint32_t a0, a1, a2, a3;
            ldsm4(a0, a1, a2, a3, su(&Qs[m0 + al][kb + ah]));
            #pragma unroll
            for (int jj = 0; jj < 8; jj += 2) {
                uint32_t b0, b1, b2, b3;
                int row  = (jj + (bg >> 1)) * 8 + b4;
                int colb = kb + (bg & 1) * 8;
                ldsm4(b0, b1, b2, b3, su(&Ks[row][colb]));
                mma16816(Sf[jj],     a0, a1, a2, a3, b0, b1);
                mma16816(Sf[jj + 1], a0, a1, a2, a3, b2, b3);
            }
        }

        // ---- online softmax (register + shuffle) ----
        float mx0 = -1e30f, mx1 = -1e30f;
        #pragma unroll
        for (int j = 0; j < 8; j++) {
            mx0 = fmaxf(mx0, fmaxf(Sf[j][0], Sf[j][1]));
            mx1 = fmaxf(mx1, fmaxf(Sf[j][2], Sf[j][3]));
        }
        mx0 = fmaxf(mx0, __shfl_xor_sync(0xffffffffu, mx0, 1));
        mx0 = fmaxf(mx0, __shfl_xor_sync(0xffffffffu, mx0, 2));
        mx1 = fmaxf(mx1, __shfl_xor_sync(0xffffffffu, mx1, 1));
        mx1 = fmaxf(mx1, __shfl_xor_sync(0xffffffffu, mx1, 2));
        float mn0 = fmaxf(mrow[0], mx0), mn1 = fmaxf(mrow[1], mx1);
        float al0 = __expf(mrow[0] - mn0), al1 = __expf(mrow[1] - mn1);
        mrow[0] = mn0; mrow[1] = mn1;

        float s0 = 0.f, s1 = 0.f;
        #pragma unroll
        for (int j = 0; j < 8; j++) {
            Sf[j][0] = __expf(Sf[j][0] - mn0);
            Sf[j][1] = __expf(Sf[j][1] - mn0);
            Sf[j][2] = __expf(Sf[j][2] - mn1);
            Sf[j][3] = __expf(Sf[j][3] - mn1);
            s0 += Sf[j][0] + Sf[j][1];
            s1 += Sf[j][2] + Sf[j][3];
        }
        s0 += __shfl_xor_sync(0xffffffffu, s0, 1);
        s0 += __shfl_xor_sync(0xffffffffu, s0, 2);
        s1 += __shfl_xor_sync(0xffffffffu, s1, 1);
        s1 += __shfl_xor_sync(0xffffffffu, s1, 2);
        lrow[0] = lrow[0] * al0 + s0;
        lrow[1] = lrow[1] * al1 + s1;

        #pragma unroll
        for (int nd = 0; nd < 4; nd++) {
            Of[nd][0] *= al0; Of[nd][1] *= al0;
            Of[nd][2] *= al1; Of[nd][3] *= al1;
        }

        // ---- pack P into A-fragments (hi/lo) ----
        uint32_t ph[4][4], pl[4][4];
        #pragma unroll
        for (int kc = 0; kc < 4; kc++) {
            int j0 = 2 * kc, j1 = 2 * kc + 1;
            split2(Sf[j0][0], Sf[j0][1], ph[kc][0], pl[kc][0]);
            split2(Sf[j0][2], Sf[j0][3], ph[kc][1], pl[kc][1]);
            split2(Sf[j1][0], Sf[j1][1], ph[kc][2], pl[kc][2]);
            split2(Sf[j1][2], Sf[j1][3], ph[kc][3], pl[kc][3]);
        }

        // ---- O += P V^T ----
        #pragma unroll
        for (int np = 0; np < 2; np++) {           // pairs of d n-tiles
            #pragma unroll
            for (int kc = 0; kc < 4; kc++) {
                int row  = (np * 2 + (bg >> 1)) * 8 + b4;
                int colb = kc * 16 + (bg & 1) * 8;
                uint32_t h0, h1, h2, h3, q0, q1, q2, q3;
                ldsm4(h0, h1, h2, h3, su(&Vh[row][colb]));
                ldsm4(q0, q1, q2, q3, su(&Vl[row][colb]));
                mma16816(Of[np * 2],     ph[kc][0], ph[kc][1], ph[kc][2], ph[kc][3], h0, h1);
                mma16816(Of[np * 2],     pl[kc][0], pl[kc][1], pl[kc][2], pl[kc][3], h0, h1);
                mma16816(Of[np * 2],     ph[kc][0], ph[kc][1], ph[kc][2], ph[kc][3], q0, q1);
                mma16816(Of[np * 2 + 1], ph[kc][0], ph[kc][1], ph[kc][2], ph[kc][3], h2, h3);
                mma16816(Of[np * 2 + 1], pl[kc][0], pl[kc][1], pl[kc][2], pl[kc][3], h2, h3);
                mma16816(Of[np * 2 + 1], ph[kc][0], ph[kc][1], ph[kc][2], ph[kc][3], q2, q3);
            }
        }
    }

    // ---- epilogue: normalize, transpose via smem, coalesced store ----
    float inv0 = 1.f / lrow[0], inv1 = 1.f / lrow[1];
    int r0 = lane >> 2, tig = lane & 3;
    #pragma unroll
    for (int nd = 0; nd < 4; nd++) {
        int col = nd * 8 + tig * 2;
        Os[m0 + r0][col]         = Of[nd][0] * inv0;
        Os[m0 + r0][col + 1]     = Of[nd][1] * inv0;
        Os[m0 + r0 + 8][col]     = Of[nd][2] * inv1;
        Os[m0 + r0 + 8][col + 1] = Of[nd][3] * inv1;
    }
    __syncthreads();
    float* op = g_att + ((size_t)batch * CC + h * 32) * TT;
    for (int f = tid; f < 512; f += 128) {
        int d = f >> 4, lq = (f & 15) * 4;
        float4 v = make_float4(Os[lq][d], Os[lq + 1][d], Os[lq + 2][d], Os[lq + 3][d]);
        *(float4*)(op + (size_t)d * TT + l0 + lq) = v;
    }
}

// ---------------------------------------------------------------------------
// Kernel 4: out projection + bias + residual (SIMT fp32).
// ---------------------------------------------------------------------------
__global__ void out_gemm_kernel(const float* __restrict__ A /* [256,256] */,
                                const float* __restrict__ ob,
                                const float* __restrict__ xres,
                                float* __restrict__ out) {
    int batch = blockIdx.z;
    const float* Bm = g_att + (size_t)batch * CC * TT;
    const float* Xm = xres  + (size_t)batch * CC * TT;
    float*       Cm = out   + (size_t)batch * CC * TT;
    int n0 = blockIdx.x * 64, m0 = blockIdx.y * 64;

    __shared__ __align__(16) float As[16][68];
    __shared__ __align__(16) float Bs[16][68];

    int tid = threadIdx.x;
    int ty = tid >> 4, tx = tid & 15;
    float acc[4][4] = {};

    for (int k0 = 0; k0 < CC; k0 += 16) {
        {
            int row = tid >> 2, cg = tid & 3;
            float4 a = *(const float4*)(A + (size_t)(m0 + row) * CC + k0 + cg * 4);
            As[cg * 4 + 0][row] = a.x;
            As[cg * 4 + 1][row] = a.y;
            As[cg * 4 + 2][row] = a.z;
            As[cg * 4 + 3][row] = a.w;
        }
        {
            int row = tid >> 4, cg = tid & 15;
            *(float4*)&Bs[row][cg * 4] =
                *(const float4*)(Bm + (size_t)(k0 + row) * TT + n0 + cg * 4);
        }
        __syncthreads();
        #pragma unroll
        for (int kk = 0; kk < 16; kk++) {
            float4 a  = *(const float4*)&As[kk][ty * 4];
            float4 bv = *(const float4*)&Bs[kk][tx * 4];
            acc[0][0] += a.x * bv.x; acc[0][1] += a.x * bv.y; acc[0][2] += a.x * bv.z; acc[0][3] += a.x * bv.w;
            acc[1][0] += a.y * bv.x; acc[1][1] += a.y * bv.y; acc[1][2] += a.y * bv.z; acc[1][3] += a.y * bv.w;
            acc[2][0] += a.z * bv.x; acc[2][1] += a.z * bv.y; acc[2][2] += a.z * bv.z; acc[2][3] += a.z * bv.w;
            acc[3][0] += a.w * bv.x; acc[3][1] += a.w * bv.y; acc[3][2] += a.w * bv.z; acc[3][3] += a.w * bv.w;
        }
        __syncthreads();
    }
    #pragma unroll
    for (int i = 0; i < 4; i++) {
        int m = m0 + ty * 4 + i;
        float bsv = ob[m];
        size_t off = (size_t)m * TT + n0 + tx * 4;
        float4 r = *(const float4*)(Xm + off);
        float4 o = make_float4(acc[i][0] + bsv + r.x, acc[i][1] + bsv + r.y,
                               acc[i][2] + bsv + r.z, acc[i][3] + bsv + r.w);
        *(float4*)(Cm + off) = o;
    }
}

// ---------------------------------------------------------------------------
extern "C" void kernel_launch(void* const* d_in, const int* in_sizes, int n_in,
                              void* d_out, int out_size) {
    const float* x     = (const float*)d_in[0];
    const float* gn_w  = (const float*)d_in[1];
    const float* gn_b  = (const float*)d_in[2];
    const float* qkv_w = (const float*)d_in[3];
    const float* out_w = (const float*)d_in[4];
    const float* out_b = (const float*)d_in[5];
    float* out = (float*)d_out;

    gn_kernel<<<BB * 32, 256>>>(x, gn_w, gn_b);
    qkv_gemm_kernel<<<dim3(TT / 64, M3 / 64, BB), 256>>>(qkv_w);
    attn_kernel<<<dim3(TT / 64, HH, BB), 128>>>();
    out_gemm_kernel<<<dim3(TT / 64, CC / 64, BB), 256>>>(out_w, out_b, x, out);
}

// round 3
// speedup vs baseline: 2.6230x; 1.6716x over previous
#include <cuda_runtime.h>
#include <cuda_bf16.h>
#include <cstdint>

// Shapes (fixed by the problem)
#define BB 4
#define CC 256
#define TT 2048
#define HH 8
#define DD 32
#define M3 768   // 3*C

// Scratch (device globals; no allocation in kernel_launch)
__device__ float g_norm[BB * CC * TT];                       // 8.4 MB
__device__ __nv_bfloat16 g_sph[BB * HH * 3 * DD * TT];       // 12.6 MB (hi)
__device__ __nv_bfloat16 g_spl[BB * HH * 3 * DD * TT];       // 12.6 MB (lo)
__device__ float g_att[BB * CC * TT];                        // 8.4 MB

// ---------------------------------------------------------------------------
// Helpers
// ---------------------------------------------------------------------------
__device__ __forceinline__ uint32_t su(const void* p) {
    uint32_t a;
    asm("{ .reg .u64 t; cvta.to.shared.u64 t, %1; cvt.u32.u64 %0, t; }"
        : "=r"(a) : "l"(p));
    return a;
}

__device__ __forceinline__ void ldsm4(uint32_t& d0, uint32_t& d1,
                                      uint32_t& d2, uint32_t& d3, uint32_t addr) {
    asm volatile("ldmatrix.sync.aligned.m8n8.x4.shared.b16 {%0,%1,%2,%3}, [%4];"
                 : "=r"(d0), "=r"(d1), "=r"(d2), "=r"(d3) : "r"(addr));
}

__device__ __forceinline__ void ldsm4t(uint32_t& d0, uint32_t& d1,
                                       uint32_t& d2, uint32_t& d3, uint32_t addr) {
    asm volatile("ldmatrix.sync.aligned.m8n8.x4.trans.shared.b16 {%0,%1,%2,%3}, [%4];"
                 : "=r"(d0), "=r"(d1), "=r"(d2), "=r"(d3) : "r"(addr));
}

__device__ __forceinline__ void mma16816(float* c,
                                         uint32_t a0, uint32_t a1, uint32_t a2, uint32_t a3,
                                         uint32_t b0, uint32_t b1) {
    asm volatile("mma.sync.aligned.m16n8k16.row.col.f32.bf16.bf16.f32 "
                 "{%0,%1,%2,%3}, {%4,%5,%6,%7}, {%8,%9}, {%0,%1,%2,%3};"
                 : "+f"(c[0]), "+f"(c[1]), "+f"(c[2]), "+f"(c[3])
                 : "r"(a0), "r"(a1), "r"(a2), "r"(a3), "r"(b0), "r"(b1));
}

__device__ __forceinline__ void split2(float x, float y, uint32_t& hi, uint32_t& lo) {
    __nv_bfloat16 hx = __float2bfloat16(x);
    __nv_bfloat16 hy = __float2bfloat16(y);
    float rx = x - __bfloat162float(hx);
    float ry = y - __bfloat162float(hy);
    __nv_bfloat162 H; H.x = hx; H.y = hy;
    __nv_bfloat162 L; L.x = __float2bfloat16(rx); L.y = __float2bfloat16(ry);
    hi = *(uint32_t*)&H;
    lo = *(uint32_t*)&L;
}

// ---------------------------------------------------------------------------
// Kernel 1: GroupNorm
// ---------------------------------------------------------------------------
__global__ void gn_kernel(const float* __restrict__ x,
                          const float* __restrict__ w,
                          const float* __restrict__ bias) {
    int bg = blockIdx.x;
    int bb = bg >> 5, g = bg & 31;
    const float4* xp = (const float4*)(x + ((size_t)bb * CC + g * 8) * TT);
    int tid = threadIdx.x;

    float s = 0.f, s2 = 0.f;
    for (int i = tid; i < 4096; i += 256) {
        float4 v = xp[i];
        s  += v.x + v.y + v.z + v.w;
        s2 += v.x * v.x + v.y * v.y + v.z * v.z + v.w * v.w;
    }
    __shared__ float rs[256], rs2[256];
    rs[tid] = s; rs2[tid] = s2;
    __syncthreads();
    for (int off = 128; off > 0; off >>= 1) {
        if (tid < off) { rs[tid] += rs[tid + off]; rs2[tid] += rs2[tid + off]; }
        __syncthreads();
    }
    float mu   = rs[0] * (1.f / 16384.f);
    float var  = rs2[0] * (1.f / 16384.f) - mu * mu;
    float rstd = rsqrtf(var + 1e-5f);

    float4* op = (float4*)(g_norm + ((size_t)bb * CC + g * 8) * TT);
    for (int i = tid; i < 4096; i += 256) {
        int c = g * 8 + (i >> 9);
        float wc = w[c] * rstd;
        float bc = bias[c] - mu * wc;
        float4 v = xp[i];
        float4 o;
        o.x = v.x * wc + bc;
        o.y = v.y * wc + bc;
        o.z = v.z * wc + bc;
        o.w = v.w * wc + bc;
        op[i] = o;
    }
}

// ---------------------------------------------------------------------------
// Kernel 2: QKV projection GEMM (SIMT fp32) with split-bf16 epilogue.
// Writes hi/lo bf16 arrays laid out [b][h][role(q,k,v)][d(32)][t(2048)].
// Q is pre-scaled by 1/16 before splitting.
// ---------------------------------------------------------------------------
__global__ void qkv_gemm_kernel(const float* __restrict__ A /* [768,256] */) {
    int batch = blockIdx.z;
    const float* Bm = g_norm + (size_t)batch * CC * TT;
    int n0 = blockIdx.x * 64, m0 = blockIdx.y * 64;

    __shared__ __align__(16) float As[16][68];
    __shared__ __align__(16) float Bs[16][68];

    int tid = threadIdx.x;
    int ty = tid >> 4, tx = tid & 15;
    float acc[4][4] = {};

    for (int k0 = 0; k0 < CC; k0 += 16) {
        {
            int row = tid >> 2, cg = tid & 3;
            float4 a = *(const float4*)(A + (size_t)(m0 + row) * CC + k0 + cg * 4);
            As[cg * 4 + 0][row] = a.x;
            As[cg * 4 + 1][row] = a.y;
            As[cg * 4 + 2][row] = a.z;
            As[cg * 4 + 3][row] = a.w;
        }
        {
            int row = tid >> 4, cg = tid & 15;
            *(float4*)&Bs[row][cg * 4] =
                *(const float4*)(Bm + (size_t)(k0 + row) * TT + n0 + cg * 4);
        }
        __syncthreads();
        #pragma unroll
        for (int kk = 0; kk < 16; kk++) {
            float4 a  = *(const float4*)&As[kk][ty * 4];
            float4 bv = *(const float4*)&Bs[kk][tx * 4];
            acc[0][0] += a.x * bv.x; acc[0][1] += a.x * bv.y; acc[0][2] += a.x * bv.z; acc[0][3] += a.x * bv.w;
            acc[1][0] += a.y * bv.x; acc[1][1] += a.y * bv.y; acc[1][2] += a.y * bv.z; acc[1][3] += a.y * bv.w;
            acc[2][0] += a.z * bv.x; acc[2][1] += a.z * bv.y; acc[2][2] += a.z * bv.z; acc[2][3] += a.z * bv.w;
            acc[3][0] += a.w * bv.x; acc[3][1] += a.w * bv.y; acc[3][2] += a.w * bv.z; acc[3][3] += a.w * bv.w;
        }
        __syncthreads();
    }
    #pragma unroll
    for (int i = 0; i < 4; i++) {
        int o = m0 + ty * 4 + i;
        int hh = o / 96, rr = o % 96;
        int role = rr >> 5, d = rr & 31;
        float sc = (role == 0) ? 0.0625f : 1.0f;
        size_t base = ((((size_t)batch * HH + hh) * 3 + role) * DD + d) * TT + n0 + tx * 4;
        uint32_t h01, l01, h23, l23;
        split2(acc[i][0] * sc, acc[i][1] * sc, h01, l01);
        split2(acc[i][2] * sc, acc[i][3] * sc, h23, l23);
        *(uint2*)(g_sph + base) = make_uint2(h01, h23);
        *(uint2*)(g_spl + base) = make_uint2(l01, l23);
    }
}

// ---------------------------------------------------------------------------
// Kernel 3: flash attention, precomputed split-bf16 operands.
// Block = 128 threads (4 warps); warp w owns S/O rows w*16..w*16+15.
// Smem tiles are layout-preserving copies [d(32)][t(64)] (stride 72, 144B:
// 16B-aligned rows, conflict-free ldmatrix). Q/K fragments via ldmatrix.trans,
// V via plain ldmatrix. Error-corrected products:
//   S = Qh*Kh + Ql*Kh + Qh*Kl      O += Ph*Vh + Pl*Vh + Ph*Vl
// ---------------------------------------------------------------------------
__global__ void __launch_bounds__(128) attn_kernel() {
    int lt0 = blockIdx.x * 64, h = blockIdx.y, batch = blockIdx.z;
    size_t hb = ((size_t)batch * HH + h) * 3 * DD * TT;
    const __nv_bfloat16* qhp = g_sph + hb;
    const __nv_bfloat16* khp = qhp + DD * TT;
    const __nv_bfloat16* vhp = qhp + 2 * DD * TT;
    const __nv_bfloat16* qlp = g_spl + hb;
    const __nv_bfloat16* klp = qlp + DD * TT;
    const __nv_bfloat16* vlp = qlp + 2 * DD * TT;

    __shared__ __align__(16) __nv_bfloat16 Qh[32][72], Ql[32][72];
    __shared__ __align__(16) __nv_bfloat16 Kh[32][72], Kl[32][72];
    __shared__ __align__(16) __nv_bfloat16 Vh[32][72], Vl[32][72];
    __shared__ __align__(16) float Os[64][33];

    int tid  = threadIdx.x;
    int lane = tid & 31;
    int warp = tid >> 5;
    int m0   = warp * 16;

    // Load Q tiles (once): 32 rows x 64 cols, 16B vector copies
    #pragma unroll
    for (int t2 = 0; t2 < 2; t2++) {
        int f = tid + t2 * 128;
        int d = f >> 3, c = (f & 7) * 8;
        *(uint4*)&Qh[d][c] = *(const uint4*)(qhp + (size_t)d * TT + lt0 + c);
        *(uint4*)&Ql[d][c] = *(const uint4*)(qlp + (size_t)d * TT + lt0 + c);
    }

    float mrow[2] = { -1e30f, -1e30f };
    float lrow[2] = { 0.f, 0.f };
    float Of[4][4] = {};

    // ldmatrix address components
    int a_d = ((lane >> 4) & 1) * 8 + (lane & 7);   // A trans: stored d row
    int a_c = m0 + ((lane >> 3) & 1) * 8;           // A trans: stored l col
    int b_d = ((lane >> 3) & 1) * 8 + (lane & 7);   // B-K trans: stored d row
    int b_j = (lane >> 4);                          // B-K trans: n-group add
    int b4 = lane & 7;                              // V non-trans
    int bg = lane >> 3;

    for (int xt = 0; xt < 32; xt++) {
        __syncthreads();
        int x0 = xt * 64;
        #pragma unroll
        for (int t2 = 0; t2 < 2; t2++) {
            int f = tid + t2 * 128;
            int d = f >> 3, c = (f & 7) * 8;
            size_t g = (size_t)d * TT + x0 + c;
            *(uint4*)&Kh[d][c] = *(const uint4*)(khp + g);
            *(uint4*)&Kl[d][c] = *(const uint4*)(klp + g);
            *(uint4*)&Vh[d][c] = *(const uint4*)(vhp + g);
            *(uint4*)&Vl[d][c] = *(const uint4*)(vlp + g);
        }
        __syncthreads();

        // ---- S = Q^T K (split, scale folded into Q) ----
        float Sf[8][4] = {};
        #pragma unroll
        for (int kc = 0; kc < 2; kc++) {
            int kb = kc * 16;
            uint32_t q0, q1, q2, q3, r0, r1, r2, r3;
            ldsm4t(q0, q1, q2, q3, su(&Qh[kb + a_d][a_c]));
            ldsm4t(r0, r1, r2, r3, su(&Ql[kb + a_d][a_c]));
            #pragma unroll
            for (int jj = 0; jj < 8; jj += 2) {
                int cb = (jj + b_j) * 8;
                uint32_t k0, k1, k2, k3, e0, e1, e2, e3;
                ldsm4t(k0, k1, k2, k3, su(&Kh[kb + b_d][cb]));
                ldsm4t(e0, e1, e2, e3, su(&Kl[kb + b_d][cb]));
                mma16816(Sf[jj],     q0, q1, q2, q3, k0, k1);
                mma16816(Sf[jj],     r0, r1, r2, r3, k0, k1);
                mma16816(Sf[jj],     q0, q1, q2, q3, e0, e1);
                mma16816(Sf[jj + 1], q0, q1, q2, q3, k2, k3);
                mma16816(Sf[jj + 1], r0, r1, r2, r3, k2, k3);
                mma16816(Sf[jj + 1], q0, q1, q2, q3, e2, e3);
            }
        }

        // ---- online softmax (register + shuffle) ----
        float mx0 = -1e30f, mx1 = -1e30f;
        #pragma unroll
        for (int j = 0; j < 8; j++) {
            mx0 = fmaxf(mx0, fmaxf(Sf[j][0], Sf[j][1]));
            mx1 = fmaxf(mx1, fmaxf(Sf[j][2], Sf[j][3]));
        }
        mx0 = fmaxf(mx0, __shfl_xor_sync(0xffffffffu, mx0, 1));
        mx0 = fmaxf(mx0, __shfl_xor_sync(0xffffffffu, mx0, 2));
        mx1 = fmaxf(mx1, __shfl_xor_sync(0xffffffffu, mx1, 1));
        mx1 = fmaxf(mx1, __shfl_xor_sync(0xffffffffu, mx1, 2));
        float mn0 = fmaxf(mrow[0], mx0), mn1 = fmaxf(mrow[1], mx1);
        float al0 = __expf(mrow[0] - mn0), al1 = __expf(mrow[1] - mn1);
        mrow[0] = mn0; mrow[1] = mn1;

        float s0 = 0.f, s1 = 0.f;
        #pragma unroll
        for (int j = 0; j < 8; j++) {
            Sf[j][0] = __expf(Sf[j][0] - mn0);
            Sf[j][1] = __expf(Sf[j][1] - mn0);
            Sf[j][2] = __expf(Sf[j][2] - mn1);
            Sf[j][3] = __expf(Sf[j][3] - mn1);
            s0 += Sf[j][0] + Sf[j][1];
            s1 += Sf[j][2] + Sf[j][3];
        }
        s0 += __shfl_xor_sync(0xffffffffu, s0, 1);
        s0 += __shfl_xor_sync(0xffffffffu, s0, 2);
        s1 += __shfl_xor_sync(0xffffffffu, s1, 1);
        s1 += __shfl_xor_sync(0xffffffffu, s1, 2);
        lrow[0] = lrow[0] * al0 + s0;
        lrow[1] = lrow[1] * al1 + s1;

        #pragma unroll
        for (int nd = 0; nd < 4; nd++) {
            Of[nd][0] *= al0; Of[nd][1] *= al0;
            Of[nd][2] *= al1; Of[nd][3] *= al1;
        }

        // ---- pack P into A-fragments (hi/lo) ----
        uint32_t ph[4][4], pl[4][4];
        #pragma unroll
        for (int kc = 0; kc < 4; kc++) {
            int j0 = 2 * kc, j1 = 2 * kc + 1;
            split2(Sf[j0][0], Sf[j0][1], ph[kc][0], pl[kc][0]);
            split2(Sf[j0][2], Sf[j0][3], ph[kc][1], pl[kc][1]);
            split2(Sf[j1][0], Sf[j1][1], ph[kc][2], pl[kc][2]);
            split2(Sf[j1][2], Sf[j1][3], ph[kc][3], pl[kc][3]);
        }

        // ---- O += P V^T ----
        #pragma unroll
        for (int np = 0; np < 2; np++) {
            #pragma unroll
            for (int kc = 0; kc < 4; kc++) {
                int row  = (np * 2 + (bg >> 1)) * 8 + b4;
                int colb = kc * 16 + (bg & 1) * 8;
                uint32_t h0, h1, h2, h3, u0, u1, u2, u3;
                ldsm4(h0, h1, h2, h3, su(&Vh[row][colb]));
                ldsm4(u0, u1, u2, u3, su(&Vl[row][colb]));
                mma16816(Of[np * 2],     ph[kc][0], ph[kc][1], ph[kc][2], ph[kc][3], h0, h1);
                mma16816(Of[np * 2],     pl[kc][0], pl[kc][1], pl[kc][2], pl[kc][3], h0, h1);
                mma16816(Of[np * 2],     ph[kc][0], ph[kc][1], ph[kc][2], ph[kc][3], u0, u1);
                mma16816(Of[np * 2 + 1], ph[kc][0], ph[kc][1], ph[kc][2], ph[kc][3], h2, h3);
                mma16816(Of[np * 2 + 1], pl[kc][0], pl[kc][1], pl[kc][2], pl[kc][3], h2, h3);
                mma16816(Of[np * 2 + 1], ph[kc][0], ph[kc][1], ph[kc][2], ph[kc][3], u2, u3);
            }
        }
    }

    // ---- epilogue: normalize, transpose via smem, coalesced store ----
    float inv0 = 1.f / lrow[0], inv1 = 1.f / lrow[1];
    int r0w = lane >> 2, tig = lane & 3;
    #pragma unroll
    for (int nd = 0; nd < 4; nd++) {
        int col = nd * 8 + tig * 2;
        Os[m0 + r0w][col]         = Of[nd][0] * inv0;
        Os[m0 + r0w][col + 1]     = Of[nd][1] * inv0;
        Os[m0 + r0w + 8][col]     = Of[nd][2] * inv1;
        Os[m0 + r0w + 8][col + 1] = Of[nd][3] * inv1;
    }
    __syncthreads();
    float* op = g_att + ((size_t)batch * CC + h * DD) * TT;
    for (int f = tid; f < 512; f += 128) {
        int d = f >> 4, lq = (f & 15) * 4;
        float4 v = make_float4(Os[lq][d], Os[lq + 1][d], Os[lq + 2][d], Os[lq + 3][d]);
        *(float4*)(op + (size_t)d * TT + lt0 + lq) = v;
    }
}

// ---------------------------------------------------------------------------
// Kernel 4: out projection + bias + residual (SIMT fp32).
// ---------------------------------------------------------------------------
__global__ void out_gemm_kernel(const float* __restrict__ A /* [256,256] */,
                                const float* __restrict__ ob,
                                const float* __restrict__ xres,
                                float* __restrict__ out) {
    int batch = blockIdx.z;
    const float* Bm = g_att + (size_t)batch * CC * TT;
    const float* Xm = xres  + (size_t)batch * CC * TT;
    float*       Cm = out   + (size_t)batch * CC * TT;
    int n0 = blockIdx.x * 64, m0 = blockIdx.y * 64;

    __shared__ __align__(16) float As[16][68];
    __shared__ __align__(16) float Bs[16][68];

    int tid = threadIdx.x;
    int ty = tid >> 4, tx = tid & 15;
    float acc[4][4] = {};

    for (int k0 = 0; k0 < CC; k0 += 16) {
        {
            int row = tid >> 2, cg = tid & 3;
            float4 a = *(const float4*)(A + (size_t)(m0 + row) * CC + k0 + cg * 4);
            As[cg * 4 + 0][row] = a.x;
            As[cg * 4 + 1][row] = a.y;
            As[cg * 4 + 2][row] = a.z;
            As[cg * 4 + 3][row] = a.w;
        }
        {
            int row = tid >> 4, cg = tid & 15;
            *(float4*)&Bs[row][cg * 4] =
                *(const float4*)(Bm + (size_t)(k0 + row) * TT + n0 + cg * 4);
        }
        __syncthreads();
        #pragma unroll
        for (int kk = 0; kk < 16; kk++) {
            float4 a  = *(const float4*)&As[kk][ty * 4];
            float4 bv = *(const float4*)&Bs[kk][tx * 4];
            acc[0][0] += a.x * bv.x; acc[0][1] += a.x * bv.y; acc[0][2] += a.x * bv.z; acc[0][3] += a.x * bv.w;
            acc[1][0] += a.y * bv.x; acc[1][1] += a.y * bv.y; acc[1][2] += a.y * bv.z; acc[1][3] += a.y * bv.w;
            acc[2][0] += a.z * bv.x; acc[2][1] += a.z * bv.y; acc[2][2] += a.z * bv.z; acc[2][3] += a.z * bv.w;
            acc[3][0] += a.w * bv.x; acc[3][1] += a.w * bv.y; acc[3][2] += a.w * bv.z; acc[3][3] += a.w * bv.w;
        }
        __syncthreads();
    }
    #pragma unroll
    for (int i = 0; i < 4; i++) {
        int m = m0 + ty * 4 + i;
        float bsv = ob[m];
        size_t off = (size_t)m * TT + n0 + tx * 4;
        float4 r = *(const float4*)(Xm + off);
        float4 o = make_float4(acc[i][0] + bsv + r.x, acc[i][1] + bsv + r.y,
                               acc[i][2] + bsv + r.z, acc[i][3] + bsv + r.w);
        *(float4*)(Cm + off) = o;
    }
}

// ---------------------------------------------------------------------------
extern "C" void kernel_launch(void* const* d_in, const int* in_sizes, int n_in,
                              void* d_out, int out_size) {
    const float* x     = (const float*)d_in[0];
    const float* gn_w  = (const float*)d_in[1];
    const float* gn_b  = (const float*)d_in[2];
    const float* qkv_w = (const float*)d_in[3];
    const float* out_w = (const float*)d_in[4];
    const float* out_b = (const float*)d_in[5];
    float* out = (float*)d_out;

    gn_kernel<<<BB * 32, 256>>>(x, gn_w, gn_b);
    qkv_gemm_kernel<<<dim3(TT / 64, M3 / 64, BB), 256>>>(qkv_w);
    attn_kernel<<<dim3(TT / 64, HH, BB), 128>>>();
    out_gemm_kernel<<<dim3(TT / 64, CC / 64, BB), 256>>>(out_w, out_b, x, out);
}

// round 4
// speedup vs baseline: 3.2496x; 1.2389x over previous
#include <cuda_runtime.h>
#include <cuda_bf16.h>
#include <cstdint>

// Shapes (fixed by the problem)
#define BB 4
#define CC 256
#define TT 2048
#define HH 8
#define DD 32
#define M3 768   // 3*C

// Scratch (device globals; no allocation in kernel_launch)
__device__ __nv_bfloat16 g_nh[BB * CC * TT];             // norm hi
__device__ __nv_bfloat16 g_nl[BB * CC * TT];             // norm lo
__device__ __nv_bfloat16 g_wqh[M3 * CC], g_wql[M3 * CC]; // qkv_w split
__device__ __nv_bfloat16 g_woh[CC * CC], g_wol[CC * CC]; // out_w split
__device__ __nv_bfloat16 g_sph[BB * HH * 3 * DD * TT];   // qkv split hi
__device__ __nv_bfloat16 g_spl[BB * HH * 3 * DD * TT];   // qkv split lo
__device__ __nv_bfloat16 g_ath[BB * CC * TT];            // attn out hi
__device__ __nv_bfloat16 g_atl[BB * CC * TT];            // attn out lo

// ---------------------------------------------------------------------------
// Helpers
// ---------------------------------------------------------------------------
__device__ __forceinline__ uint32_t su(const void* p) {
    uint32_t a;
    asm("{ .reg .u64 t; cvta.to.shared.u64 t, %1; cvt.u32.u64 %0, t; }"
        : "=r"(a) : "l"(p));
    return a;
}

__device__ __forceinline__ void ldsm4(uint32_t& d0, uint32_t& d1,
                                      uint32_t& d2, uint32_t& d3, uint32_t addr) {
    asm volatile("ldmatrix.sync.aligned.m8n8.x4.shared.b16 {%0,%1,%2,%3}, [%4];"
                 : "=r"(d0), "=r"(d1), "=r"(d2), "=r"(d3) : "r"(addr));
}

__device__ __forceinline__ void ldsm4t(uint32_t& d0, uint32_t& d1,
                                       uint32_t& d2, uint32_t& d3, uint32_t addr) {
    asm volatile("ldmatrix.sync.aligned.m8n8.x4.trans.shared.b16 {%0,%1,%2,%3}, [%4];"
                 : "=r"(d0), "=r"(d1), "=r"(d2), "=r"(d3) : "r"(addr));
}

__device__ __forceinline__ void mma16816(float* c,
                                         uint32_t a0, uint32_t a1, uint32_t a2, uint32_t a3,
                                         uint32_t b0, uint32_t b1) {
    asm volatile("mma.sync.aligned.m16n8k16.row.col.f32.bf16.bf16.f32 "
                 "{%0,%1,%2,%3}, {%4,%5,%6,%7}, {%8,%9}, {%0,%1,%2,%3};"
                 : "+f"(c[0]), "+f"(c[1]), "+f"(c[2]), "+f"(c[3])
                 : "r"(a0), "r"(a1), "r"(a2), "r"(a3), "r"(b0), "r"(b1));
}

__device__ __forceinline__ void split2(float x, float y, uint32_t& hi, uint32_t& lo) {
    __nv_bfloat16 hx = __float2bfloat16(x);
    __nv_bfloat16 hy = __float2bfloat16(y);
    float rx = x - __bfloat162float(hx);
    float ry = y - __bfloat162float(hy);
    __nv_bfloat162 H; H.x = hx; H.y = hy;
    __nv_bfloat162 L; L.x = __float2bfloat16(rx); L.y = __float2bfloat16(ry);
    hi = *(uint32_t*)&H;
    lo = *(uint32_t*)&L;
}

__device__ __forceinline__ void split1(float x, __nv_bfloat16& h, __nv_bfloat16& l) {
    h = __float2bfloat16(x);
    l = __float2bfloat16(x - __bfloat162float(h));
}

// ---------------------------------------------------------------------------
// Kernel 0: split weights into bf16 hi/lo (cheap, once per launch)
// ---------------------------------------------------------------------------
__global__ void split_w(const float* __restrict__ qw, const float* __restrict__ ow) {
    int i = blockIdx.x * 256 + threadIdx.x;
    if (i < M3 * CC) {
        split1(qw[i], g_wqh[i], g_wql[i]);
    }
    if (i < CC * CC) {
        split1(ow[i], g_woh[i], g_wol[i]);
    }
}

// ---------------------------------------------------------------------------
// Kernel 1: GroupNorm -> split bf16 [b][c][t]
// ---------------------------------------------------------------------------
__global__ void gn_kernel(const float* __restrict__ x,
                          const float* __restrict__ w,
                          const float* __restrict__ bias) {
    int bg = blockIdx.x;
    int bb = bg >> 5, g = bg & 31;
    const float4* xp = (const float4*)(x + ((size_t)bb * CC + g * 8) * TT);
    int tid = threadIdx.x;

    float s = 0.f, s2 = 0.f;
    for (int i = tid; i < 4096; i += 256) {
        float4 v = xp[i];
        s  += v.x + v.y + v.z + v.w;
        s2 += v.x * v.x + v.y * v.y + v.z * v.z + v.w * v.w;
    }
    __shared__ float rs[256], rs2[256];
    rs[tid] = s; rs2[tid] = s2;
    __syncthreads();
    for (int off = 128; off > 0; off >>= 1) {
        if (tid < off) { rs[tid] += rs[tid + off]; rs2[tid] += rs2[tid + off]; }
        __syncthreads();
    }
    float mu   = rs[0] * (1.f / 16384.f);
    float var  = rs2[0] * (1.f / 16384.f) - mu * mu;
    float rstd = rsqrtf(var + 1e-5f);

    size_t ob = ((size_t)bb * CC + g * 8) * TT;
    for (int i = tid; i < 4096; i += 256) {
        int c = g * 8 + (i >> 9);
        float wc = w[c] * rstd;
        float bc = bias[c] - mu * wc;
        float4 v = xp[i];
        uint32_t h01, l01, h23, l23;
        split2(v.x * wc + bc, v.y * wc + bc, h01, l01);
        split2(v.z * wc + bc, v.w * wc + bc, h23, l23);
        *(uint2*)(g_nh + ob + (size_t)i * 4) = make_uint2(h01, h23);
        *(uint2*)(g_nl + ob + (size_t)i * 4) = make_uint2(l01, l23);
    }
}

// ---------------------------------------------------------------------------
// Kernel 2: QKV projection, split-bf16 mma GEMM.
// Block 256 threads (8 warps): tile M=128 (warp = m16), N=64, K-step 32.
// A = qkv_w split [m][k], B = norm split [k][t].
// C = Ah*Bh + Al*Bh + Ah*Bl. Epilogue: scale Q by 1/16, split, write
// [b][h][role][d][t] layout.
// ---------------------------------------------------------------------------
__global__ void __launch_bounds__(256) qkv_gemm_kernel() {
    int batch = blockIdx.z;
    int n0 = blockIdx.x * 64, mb = blockIdx.y * 128;
    const __nv_bfloat16* Bh_g = g_nh + (size_t)batch * CC * TT;
    const __nv_bfloat16* Bl_g = g_nl + (size_t)batch * CC * TT;

    __shared__ __align__(16) __nv_bfloat16 Ah[128][40], Al[128][40];
    __shared__ __align__(16) __nv_bfloat16 Bh[32][72],  Bl[32][72];

    int tid  = threadIdx.x;
    int lane = tid & 31;
    int warp = tid >> 5;
    int m0   = warp * 16;

    float Sf[8][4] = {};

    int a_r = lane & 15, a_h = (lane >> 4) * 8;       // A non-trans
    int b_d = ((lane >> 3) & 1) * 8 + (lane & 7);     // B trans
    int b_j = (lane >> 4);

    for (int k0 = 0; k0 < CC; k0 += 32) {
        __syncthreads();
        {   // A tile 128x32 hi/lo
            #pragma unroll
            for (int t2 = 0; t2 < 2; t2++) {
                int f = tid + t2 * 256;
                int r = f >> 2, c = (f & 3) * 8;
                size_t g = (size_t)(mb + r) * CC + k0 + c;
                *(uint4*)&Ah[r][c] = *(const uint4*)(g_wqh + g);
                *(uint4*)&Al[r][c] = *(const uint4*)(g_wql + g);
            }
            // B tile 32x64 hi/lo
            int r = tid >> 3, c = (tid & 7) * 8;
            size_t g = (size_t)(k0 + r) * TT + n0 + c;
            *(uint4*)&Bh[r][c] = *(const uint4*)(Bh_g + g);
            *(uint4*)&Bl[r][c] = *(const uint4*)(Bl_g + g);
        }
        __syncthreads();
        #pragma unroll
        for (int kc = 0; kc < 2; kc++) {
            int kb = kc * 16;
            uint32_t a0, a1, a2, a3, c0, c1, c2, c3;
            ldsm4(a0, a1, a2, a3, su(&Ah[m0 + a_r][kb + a_h]));
            ldsm4(c0, c1, c2, c3, su(&Al[m0 + a_r][kb + a_h]));
            #pragma unroll
            for (int jj = 0; jj < 8; jj += 2) {
                int cb = (jj + b_j) * 8;
                uint32_t k0r, k1r, k2r, k3r, e0, e1, e2, e3;
                ldsm4t(k0r, k1r, k2r, k3r, su(&Bh[kb + b_d][cb]));
                ldsm4t(e0, e1, e2, e3, su(&Bl[kb + b_d][cb]));
                mma16816(Sf[jj],     a0, a1, a2, a3, k0r, k1r);
                mma16816(Sf[jj],     c0, c1, c2, c3, k0r, k1r);
                mma16816(Sf[jj],     a0, a1, a2, a3, e0, e1);
                mma16816(Sf[jj + 1], a0, a1, a2, a3, k2r, k3r);
                mma16816(Sf[jj + 1], c0, c1, c2, c3, k2r, k3r);
                mma16816(Sf[jj + 1], a0, a1, a2, a3, e2, e3);
            }
        }
    }

    // Epilogue: rows mb+m0+r0 and +8; cols n0 + jj*8 + tig*2.
    int r0 = lane >> 2, tig = lane & 3;
    #pragma unroll
    for (int half = 0; half < 2; half++) {
        int o = mb + m0 + r0 + half * 8;
        int hh = o / 96, rr = o % 96;
        int role = rr >> 5, d = rr & 31;
        float sc = (role == 0) ? 0.0625f : 1.0f;
        size_t base = ((((size_t)batch * HH + hh) * 3 + role) * DD + d) * TT + n0 + tig * 2;
        #pragma unroll
        for (int j = 0; j < 8; j++) {
            uint32_t hv, lv;
            split2(Sf[j][2 * half] * sc, Sf[j][2 * half + 1] * sc, hv, lv);
            *(uint32_t*)(g_sph + base + j * 8) = hv;
            *(uint32_t*)(g_spl + base + j * 8) = lv;
        }
    }
}

// ---------------------------------------------------------------------------
// Kernel 3: flash attention (as R2), epilogue writes split bf16.
// ---------------------------------------------------------------------------
__global__ void __launch_bounds__(128) attn_kernel() {
    int lt0 = blockIdx.x * 64, h = blockIdx.y, batch = blockIdx.z;
    size_t hb = ((size_t)batch * HH + h) * 3 * DD * TT;
    const __nv_bfloat16* qhp = g_sph + hb;
    const __nv_bfloat16* khp = qhp + DD * TT;
    const __nv_bfloat16* vhp = qhp + 2 * DD * TT;
    const __nv_bfloat16* qlp = g_spl + hb;
    const __nv_bfloat16* klp = qlp + DD * TT;
    const __nv_bfloat16* vlp = qlp + 2 * DD * TT;

    __shared__ __align__(16) __nv_bfloat16 Qh[32][72], Ql[32][72];
    __shared__ __align__(16) __nv_bfloat16 Kh[32][72], Kl[32][72];
    __shared__ __align__(16) __nv_bfloat16 Vh[32][72], Vl[32][72];
    __shared__ __align__(16) float Os[64][33];

    int tid  = threadIdx.x;
    int lane = tid & 31;
    int warp = tid >> 5;
    int m0   = warp * 16;

    #pragma unroll
    for (int t2 = 0; t2 < 2; t2++) {
        int f = tid + t2 * 128;
        int d = f >> 3, c = (f & 7) * 8;
        *(uint4*)&Qh[d][c] = *(const uint4*)(qhp + (size_t)d * TT + lt0 + c);
        *(uint4*)&Ql[d][c] = *(const uint4*)(qlp + (size_t)d * TT + lt0 + c);
    }

    float mrow[2] = { -1e30f, -1e30f };
    float lrow[2] = { 0.f, 0.f };
    float Of[4][4] = {};

    int a_d = ((lane >> 4) & 1) * 8 + (lane & 7);
    int a_c = m0 + ((lane >> 3) & 1) * 8;
    int b_d = ((lane >> 3) & 1) * 8 + (lane & 7);
    int b_j = (lane >> 4);
    int b4 = lane & 7;
    int bg = lane >> 3;

    for (int xt = 0; xt < 32; xt++) {
        __syncthreads();
        int x0 = xt * 64;
        #pragma unroll
        for (int t2 = 0; t2 < 2; t2++) {
            int f = tid + t2 * 128;
            int d = f >> 3, c = (f & 7) * 8;
            size_t g = (size_t)d * TT + x0 + c;
            *(uint4*)&Kh[d][c] = *(const uint4*)(khp + g);
            *(uint4*)&Kl[d][c] = *(const uint4*)(klp + g);
            *(uint4*)&Vh[d][c] = *(const uint4*)(vhp + g);
            *(uint4*)&Vl[d][c] = *(const uint4*)(vlp + g);
        }
        __syncthreads();

        float Sf[8][4] = {};
        #pragma unroll
        for (int kc = 0; kc < 2; kc++) {
            int kb = kc * 16;
            uint32_t q0, q1, q2, q3, r0, r1, r2, r3;
            ldsm4t(q0, q1, q2, q3, su(&Qh[kb + a_d][a_c]));
            ldsm4t(r0, r1, r2, r3, su(&Ql[kb + a_d][a_c]));
            #pragma unroll
            for (int jj = 0; jj < 8; jj += 2) {
                int cb = (jj + b_j) * 8;
                uint32_t k0, k1, k2, k3, e0, e1, e2, e3;
                ldsm4t(k0, k1, k2, k3, su(&Kh[kb + b_d][cb]));
                ldsm4t(e0, e1, e2, e3, su(&Kl[kb + b_d][cb]));
                mma16816(Sf[jj],     q0, q1, q2, q3, k0, k1);
                mma16816(Sf[jj],     r0, r1, r2, r3, k0, k1);
                mma16816(Sf[jj],     q0, q1, q2, q3, e0, e1);
                mma16816(Sf[jj + 1], q0, q1, q2, q3, k2, k3);
                mma16816(Sf[jj + 1], r0, r1, r2, r3, k2, k3);
                mma16816(Sf[jj + 1], q0, q1, q2, q3, e2, e3);
            }
        }

        float mx0 = -1e30f, mx1 = -1e30f;
        #pragma unroll
        for (int j = 0; j < 8; j++) {
            mx0 = fmaxf(mx0, fmaxf(Sf[j][0], Sf[j][1]));
            mx1 = fmaxf(mx1, fmaxf(Sf[j][2], Sf[j][3]));
        }
        mx0 = fmaxf(mx0, __shfl_xor_sync(0xffffffffu, mx0, 1));
        mx0 = fmaxf(mx0, __shfl_xor_sync(0xffffffffu, mx0, 2));
        mx1 = fmaxf(mx1, __shfl_xor_sync(0xffffffffu, mx1, 1));
        mx1 = fmaxf(mx1, __shfl_xor_sync(0xffffffffu, mx1, 2));
        float mn0 = fmaxf(mrow[0], mx0), mn1 = fmaxf(mrow[1], mx1);
        float al0 = __expf(mrow[0] - mn0), al1 = __expf(mrow[1] - mn1);
        mrow[0] = mn0; mrow[1] = mn1;

        float s0 = 0.f, s1 = 0.f;
        #pragma unroll
        for (int j = 0; j < 8; j++) {
            Sf[j][0] = __expf(Sf[j][0] - mn0);
            Sf[j][1] = __expf(Sf[j][1] - mn0);
            Sf[j][2] = __expf(Sf[j][2] - mn1);
            Sf[j][3] = __expf(Sf[j][3] - mn1);
            s0 += Sf[j][0] + Sf[j][1];
            s1 += Sf[j][2] + Sf[j][3];
        }
        s0 += __shfl_xor_sync(0xffffffffu, s0, 1);
        s0 += __shfl_xor_sync(0xffffffffu, s0, 2);
        s1 += __shfl_xor_sync(0xffffffffu, s1, 1);
        s1 += __shfl_xor_sync(0xffffffffu, s1, 2);
        lrow[0] = lrow[0] * al0 + s0;
        lrow[1] = lrow[1] * al1 + s1;

        #pragma unroll
        for (int nd = 0; nd < 4; nd++) {
            Of[nd][0] *= al0; Of[nd][1] *= al0;
            Of[nd][2] *= al1; Of[nd][3] *= al1;
        }

        uint32_t ph[4][4], pl[4][4];
        #pragma unroll
        for (int kc = 0; kc < 4; kc++) {
            int j0 = 2 * kc, j1 = 2 * kc + 1;
            split2(Sf[j0][0], Sf[j0][1], ph[kc][0], pl[kc][0]);
            split2(Sf[j0][2], Sf[j0][3], ph[kc][1], pl[kc][1]);
            split2(Sf[j1][0], Sf[j1][1], ph[kc][2], pl[kc][2]);
            split2(Sf[j1][2], Sf[j1][3], ph[kc][3], pl[kc][3]);
        }

        #pragma unroll
        for (int np = 0; np < 2; np++) {
            #pragma unroll
            for (int kc = 0; kc < 4; kc++) {
                int row  = (np * 2 + (bg >> 1)) * 8 + b4;
                int colb = kc * 16 + (bg & 1) * 8;
                uint32_t h0, h1, h2, h3, u0, u1, u2, u3;
                ldsm4(h0, h1, h2, h3, su(&Vh[row][colb]));
                ldsm4(u0, u1, u2, u3, su(&Vl[row][colb]));
                mma16816(Of[np * 2],     ph[kc][0], ph[kc][1], ph[kc][2], ph[kc][3], h0, h1);
                mma16816(Of[np * 2],     pl[kc][0], pl[kc][1], pl[kc][2], pl[kc][3], h0, h1);
                mma16816(Of[np * 2],     ph[kc][0], ph[kc][1], ph[kc][2], ph[kc][3], u0, u1);
                mma16816(Of[np * 2 + 1], ph[kc][0], ph[kc][1], ph[kc][2], ph[kc][3], h2, h3);
                mma16816(Of[np * 2 + 1], pl[kc][0], pl[kc][1], pl[kc][2], pl[kc][3], h2, h3);
                mma16816(Of[np * 2 + 1], ph[kc][0], ph[kc][1], ph[kc][2], ph[kc][3], u2, u3);
            }
        }
    }

    // epilogue: normalize, transpose via smem, split bf16 store
    float inv0 = 1.f / lrow[0], inv1 = 1.f / lrow[1];
    int r0w = lane >> 2, tig = lane & 3;
    #pragma unroll
    for (int nd = 0; nd < 4; nd++) {
        int col = nd * 8 + tig * 2;
        Os[m0 + r0w][col]         = Of[nd][0] * inv0;
        Os[m0 + r0w][col + 1]     = Of[nd][1] * inv0;
        Os[m0 + r0w + 8][col]     = Of[nd][2] * inv1;
        Os[m0 + r0w + 8][col + 1] = Of[nd][3] * inv1;
    }
    __syncthreads();
    size_t ob = ((size_t)batch * CC + h * DD) * TT;
    for (int f = tid; f < 512; f += 128) {
        int d = f >> 4, lq = (f & 15) * 4;
        uint32_t h01, l01, h23, l23;
        split2(Os[lq][d],     Os[lq + 1][d], h01, l01);
        split2(Os[lq + 2][d], Os[lq + 3][d], h23, l23);
        size_t g = ob + (size_t)d * TT + lt0 + lq;
        *(uint2*)(g_ath + g) = make_uint2(h01, h23);
        *(uint2*)(g_atl + g) = make_uint2(l01, l23);
    }
}

// ---------------------------------------------------------------------------
// Kernel 4: out projection mma GEMM + bias + residual.
// Same structure as qkv_gemm: M=256, tile 128x64, K=256.
// ---------------------------------------------------------------------------
__global__ void __launch_bounds__(256) out_gemm_kernel(const float* __restrict__ ob,
                                                       const float* __restrict__ xres,
                                                       float* __restrict__ out) {
    int batch = blockIdx.z;
    int n0 = blockIdx.x * 64, mb = blockIdx.y * 128;
    const __nv_bfloat16* Bh_g = g_ath + (size_t)batch * CC * TT;
    const __nv_bfloat16* Bl_g = g_atl + (size_t)batch * CC * TT;

    __shared__ __align__(16) __nv_bfloat16 Ah[128][40], Al[128][40];
    __shared__ __align__(16) __nv_bfloat16 Bh[32][72],  Bl[32][72];

    int tid  = threadIdx.x;
    int lane = tid & 31;
    int warp = tid >> 5;
    int m0   = warp * 16;

    float Sf[8][4] = {};

    int a_r = lane & 15, a_h = (lane >> 4) * 8;
    int b_d = ((lane >> 3) & 1) * 8 + (lane & 7);
    int b_j = (lane >> 4);

    for (int k0 = 0; k0 < CC; k0 += 32) {
        __syncthreads();
        {
            #pragma unroll
            for (int t2 = 0; t2 < 2; t2++) {
                int f = tid + t2 * 256;
                int r = f >> 2, c = (f & 3) * 8;
                size_t g = (size_t)(mb + r) * CC + k0 + c;
                *(uint4*)&Ah[r][c] = *(const uint4*)(g_woh + g);
                *(uint4*)&Al[r][c] = *(const uint4*)(g_wol + g);
            }
            int r = tid >> 3, c = (tid & 7) * 8;
            size_t g = (size_t)(k0 + r) * TT + n0 + c;
            *(uint4*)&Bh[r][c] = *(const uint4*)(Bh_g + g);
            *(uint4*)&Bl[r][c] = *(const uint4*)(Bl_g + g);
        }
        __syncthreads();
        #pragma unroll
        for (int kc = 0; kc < 2; kc++) {
            int kb = kc * 16;
            uint32_t a0, a1, a2, a3, c0, c1, c2, c3;
            ldsm4(a0, a1, a2, a3, su(&Ah[m0 + a_r][kb + a_h]));
            ldsm4(c0, c1, c2, c3, su(&Al[m0 + a_r][kb + a_h]));
            #pragma unroll
            for (int jj = 0; jj < 8; jj += 2) {
                int cb = (jj + b_j) * 8;
                uint32_t k0r, k1r, k2r, k3r, e0, e1, e2, e3;
                ldsm4t(k0r, k1r, k2r, k3r, su(&Bh[kb + b_d][cb]));
                ldsm4t(e0, e1, e2, e3, su(&Bl[kb + b_d][cb]));
                mma16816(Sf[jj],     a0, a1, a2, a3, k0r, k1r);
                mma16816(Sf[jj],     c0, c1, c2, c3, k0r, k1r);
                mma16816(Sf[jj],     a0, a1, a2, a3, e0, e1);
                mma16816(Sf[jj + 1], a0, a1, a2, a3, k2r, k3r);
                mma16816(Sf[jj + 1], c0, c1, c2, c3, k2r, k3r);
                mma16816(Sf[jj + 1], a0, a1, a2, a3, e2, e3);
            }
        }
    }

    // Epilogue: bias + residual, fp32 out
    int r0 = lane >> 2, tig = lane & 3;
    #pragma unroll
    for (int half = 0; half < 2; half++) {
        int m = mb + m0 + r0 + half * 8;
        float bsv = ob[m];
        size_t rowoff = ((size_t)batch * CC + m) * TT + n0 + tig * 2;
        #pragma unroll
        for (int j = 0; j < 8; j++) {
            float2 r = *(const float2*)(xres + rowoff + j * 8);
            float2 o = make_float2(Sf[j][2 * half] + bsv + r.x,
                                   Sf[j][2 * half + 1] + bsv + r.y);
            *(float2*)(out + rowoff + j * 8) = o;
        }
    }
}

// ---------------------------------------------------------------------------
extern "C" void kernel_launch(void* const* d_in, const int* in_sizes, int n_in,
                              void* d_out, int out_size) {
    const float* x     = (const float*)d_in[0];
    const float* gn_w  = (const float*)d_in[1];
    const float* gn_b  = (const float*)d_in[2];
    const float* qkv_w = (const float*)d_in[3];
    const float* out_w = (const float*)d_in[4];
    const float* out_b = (const float*)d_in[5];
    float* out = (float*)d_out;

    split_w<<<M3 * CC / 256, 256>>>(qkv_w, out_w);
    gn_kernel<<<BB * 32, 256>>>(x, gn_w, gn_b);
    qkv_gemm_kernel<<<dim3(TT / 64, M3 / 128, BB), 256>>>();
    attn_kernel<<<dim3(TT / 64, HH, BB), 128>>>();
    out_gemm_kernel<<<dim3(TT / 64, CC / 128, BB), 256>>>(out_b, x, out);
}